// round 5
// baseline (speedup 1.0000x reference)
#include <cuda_runtime.h>
#include <cuda_bf16.h>

// Problem shapes (fixed by the dataset)
#define B_  128
#define P_  4096
#define L_  128
#define TPB 256
#define BLOCKS_PER_B (P_ / TPB)     // 16
#define NBLOCKS (B_ * BLOCKS_PER_B) // 2048

// Fixed scratch for deterministic two-phase reduction (no device allocs allowed)
__device__ float g_partials[NBLOCKS];

__device__ __forceinline__ float huber1(float e) {
    float a = fabsf(e);
    return (a <= 1.0f) ? 0.5f * e * e : a - 0.5f;
}

__global__ __launch_bounds__(TPB, 8)
void classifier_loss_kernel(const float* __restrict__ cls,
                            const float* __restrict__ deltas,
                            const float* __restrict__ roi,
                            const float* __restrict__ labels,
                            const int*   __restrict__ neg_flag)
{
    __shared__ float4 s_box[L_];   // lx, ly, lx+lw, ly+lh
    __shared__ float  s_area[L_];  // lw*lh
    __shared__ float2 s_wh[L_];    // lw, lh (for matched targets)
    __shared__ float  s_red[TPB];

    const int tid = threadIdx.x;
    const int b   = blockIdx.y;
    const int p   = blockIdx.x * TPB + tid;

    // Stage labels for this batch into shared (broadcast reads in the hot loop)
    if (tid < L_) {
        float4 v = ((const float4*)(labels + (size_t)b * L_ * 4))[tid];
        s_box[tid]  = make_float4(v.x, v.y, v.x + v.z, v.y + v.w);
        s_area[tid] = v.z * v.w;
        s_wh[tid]   = make_float2(v.z, v.w);
    }
    __syncthreads();

    // Proposal in image coords (SCALE = 32, exact power-of-two multiply)
    float4 r = ((const float4*)(roi + (size_t)b * P_ * 4))[p];
    const float rx = r.x * 32.0f, ry = r.y * 32.0f;
    const float rw = r.z * 32.0f, rh = r.w * 32.0f;
    const float rx2 = rx + rw, ry2 = ry + rh;
    const float rarea = rw * rh;

    // Argmax over labels of iou = inter/union, tracked via cross-multiplication
    // (union > 0 always: rarea >= 1024). First-max semantics via strict '>'.
    float bi = 0.0f;   // best inter
    float bu = 1.0f;   // best union
    int   bidx = 0;
#pragma unroll 8
    for (int l = 0; l < L_; ++l) {
        float4 lb = s_box[l];
        float  la = s_area[l];
        float ix = fminf(lb.z, rx2) - fmaxf(lb.x, rx);
        float iy = fminf(lb.w, ry2) - fmaxf(lb.y, ry);
        ix = fmaxf(ix, 0.0f);
        iy = fmaxf(iy, 0.0f);
        float inter = ix * iy;
        float uni   = (la + rarea) - inter;
        if (inter * bu > bi * uni) { bi = inter; bu = uni; bidx = l; }
    }

    // 2-class softmax cross-entropy terms
    const float* cb = cls + (size_t)b * 2 * P_;
    float l0 = cb[p];
    float l1 = cb[P_ + p];
    float mx = fmaxf(l0, l1);
    float e0 = __expf(l0 - mx);
    float e1 = __expf(l1 - mx);
    float inv = __fdividef(1.0f, e0 + e1);
    float p0 = e0 * inv, p1 = e1 * inv;
    const float LOG01 = -2.3025850929940457f;   // log(0.1)
    const float LOG09 = -0.10536051565782628f;  // log(0.9)

    // pos = any_hit && (argmax index > 0)   [reference: match > 0, strictly]
    bool pos = (bi > 0.0f) && (bidx > 0);

    float per;
    if (pos) {
        float ce_pos = -(p0 * LOG01 + p1 * LOG09);
        float4 mb  = s_box[bidx];
        float2 mwh = s_wh[bidx];
        float invw = __fdividef(1.0f, rw);
        float invh = __fdividef(1.0f, rh);
        float tx = (mb.x - rx) * invw;
        float ty = (mb.y - ry) * invh;
        float tw = __logf(fmaxf(mwh.x * invw, 1e-8f));
        float th = __logf(fmaxf(mwh.y * invh, 1e-8f));
        const float* db = deltas + (size_t)b * 4 * P_;
        float hx = huber1(tx - db[p]);
        float hy = huber1(ty - db[P_ + p]);
        float hw = huber1(tw - db[2 * P_ + p]);
        float hh = huber1(th - db[3 * P_ + p]);
        float huber = 0.25f * (hx + hy + hw + hh);
        per = 2.0f * huber + ce_pos;
    } else {
        float ce_neg = -(p0 * LOG09 + p1 * LOG01);
        per = (__ldg(neg_flag) > 0) ? ce_neg : 0.0f;
    }

    // Deterministic block reduction
    s_red[tid] = per;
    __syncthreads();
#pragma unroll
    for (int s = TPB / 2; s > 0; s >>= 1) {
        if (tid < s) s_red[tid] += s_red[tid + s];
        __syncthreads();
    }
    if (tid == 0)
        g_partials[b * BLOCKS_PER_B + blockIdx.x] = s_red[0];
}

__global__ __launch_bounds__(256)
void final_reduce_kernel(float* __restrict__ out)
{
    __shared__ double s[256];
    double acc = 0.0;
    for (int i = threadIdx.x; i < NBLOCKS; i += 256)
        acc += (double)g_partials[i];
    s[threadIdx.x] = acc;
    __syncthreads();
#pragma unroll
    for (int st = 128; st > 0; st >>= 1) {
        if (threadIdx.x < st) s[threadIdx.x] += s[threadIdx.x + st];
        __syncthreads();
    }
    if (threadIdx.x == 0) out[0] = (float)s[0];
}

extern "C" void kernel_launch(void* const* d_in, const int* in_sizes, int n_in,
                              void* d_out, int out_size)
{
    const float* cls    = (const float*)d_in[0];  // [B, 2P]
    const float* deltas = (const float*)d_in[1];  // [B, 4P]
    const float* roi    = (const float*)d_in[2];  // [B, P, 4]
    const float* labels = (const float*)d_in[3];  // [B, L, 4]
    const int*   negf   = (const int*)  d_in[4];  // scalar

    dim3 grid(BLOCKS_PER_B, B_);
    classifier_loss_kernel<<<grid, TPB>>>(cls, deltas, roi, labels, negf);
    final_reduce_kernel<<<1, 256>>>((float*)d_out);
    (void)in_sizes; (void)n_in; (void)out_size;
}

// round 6
// speedup vs baseline: 1.3628x; 1.3628x over previous
#include <cuda_runtime.h>
#include <cuda_bf16.h>

// Problem shapes (fixed by the dataset)
#define B_   128
#define P_   4096
#define L_   128
#define TPB  256
#define PPT  2                          // proposals per thread
#define BLOCKS_PER_B (P_ / (TPB * PPT)) // 8
#define NB   (B_ * BLOCKS_PER_B)        // 1024 partials

__device__ float        g_partials[NB];
__device__ unsigned int g_count = 0;

__device__ __forceinline__ float huber1(float e) {
    float a = fabsf(e);
    return (a <= 1.0f) ? 0.5f * e * e : a - 0.5f;
}

__device__ __forceinline__ float frcp(float x) {
    float r;
    asm("rcp.approx.f32 %0, %1;" : "=f"(r) : "f"(x));
    return r;
}

__global__ __launch_bounds__(TPB, 4)
void classifier_loss_kernel(const float* __restrict__ cls,
                            const float* __restrict__ deltas,
                            const float* __restrict__ roi,
                            const float* __restrict__ labels,
                            const int*   __restrict__ neg_flag,
                            float*       __restrict__ out)
{
    __shared__ float4 s_box[L_];   // lx, ly, lx+lw, ly+lh
    __shared__ float  s_area[L_];  // lw*lh
    __shared__ float2 s_wh[L_];    // lw, lh (exact, for targets)
    __shared__ float  s_red[TPB];
    __shared__ bool   s_last;
    __shared__ double s_d[TPB];

    const int tid = threadIdx.x;
    const int b   = blockIdx.y;
    const int p0  = blockIdx.x * (TPB * PPT) + tid;   // proposal A
    const int p1  = p0 + TPB;                         // proposal B

    if (tid < L_) {
        float4 v = ((const float4*)(labels + (size_t)b * L_ * 4))[tid];
        s_box[tid]  = make_float4(v.x, v.y, v.x + v.z, v.y + v.w);
        s_area[tid] = v.z * v.w;
        s_wh[tid]   = make_float2(v.z, v.w);
    }
    __syncthreads();

    // Proposals in image coords (SCALE=32 is an exact pow2 multiply)
    float4 ra = ((const float4*)(roi + (size_t)b * P_ * 4))[p0];
    float4 rb = ((const float4*)(roi + (size_t)b * P_ * 4))[p1];
    const float arx = ra.x * 32.0f, ary = ra.y * 32.0f, arw = ra.z * 32.0f, arh = ra.w * 32.0f;
    const float brx = rb.x * 32.0f, bry = rb.y * 32.0f, brw = rb.z * 32.0f, brh = rb.w * 32.0f;
    const float arx2 = arx + arw, ary2 = ary + arh, aA = arw * arh;
    const float brx2 = brx + brw, bry2 = bry + brh, bA = brw * brh;

    // argmax_l iou = argmax_l inter/(la + rarea)   (monotone transform of iou)
    // Packed argmax: high 25 bits = score bits, low 7 bits = (127 - l) so the
    // FIRST max index wins ties under unsigned max (matches jnp.argmax).
    unsigned bestA = 0u, bestB = 0u;
#pragma unroll 8
    for (int l = 0; l < L_; ++l) {
        float4 lb = s_box[l];
        float  la = s_area[l];
        unsigned tag = (unsigned)(127 - l);

        float ax = fminf(lb.z, arx2) - fmaxf(lb.x, arx);
        float ay = fminf(lb.w, ary2) - fmaxf(lb.y, ary);
        float ai = fmaxf(ax, 0.0f) * fmaxf(ay, 0.0f);
        float asc = ai * frcp(la + aA);
        unsigned apk = (__float_as_uint(asc) & 0xFFFFFF80u) | tag;
        bestA = max(bestA, apk);

        float bx = fminf(lb.z, brx2) - fmaxf(lb.x, brx);
        float by = fminf(lb.w, bry2) - fmaxf(lb.y, bry);
        float bi = fmaxf(bx, 0.0f) * fmaxf(by, 0.0f);
        float bsc = bi * frcp(la + bA);
        unsigned bpk = (__float_as_uint(bsc) & 0xFFFFFF80u) | tag;
        bestB = max(bestB, bpk);
    }

    const int neg = __ldg(neg_flag);
    const float LOG01 = -2.3025850929940457f;   // log(0.1)
    const float LOG09 = -0.10536051565782628f;  // log(0.9)
    const float* cb = cls    + (size_t)b * 2 * P_;
    const float* db = deltas + (size_t)b * 4 * P_;

    float per_sum = 0.0f;

#pragma unroll
    for (int q = 0; q < PPT; ++q) {
        const int   p     = q ? p1 : p0;
        const unsigned be = q ? bestB : bestA;
        const float rx = q ? brx : arx, ry = q ? bry : ary;
        const float rw = q ? brw : arw, rh = q ? brh : arh;

        int  bidx = 127 - (int)(be & 0x7Fu);
        bool pos  = ((be & 0xFFFFFF80u) != 0u) && (bidx > 0);

        float l0 = cb[p];
        float l1 = cb[P_ + p];
        float mx = fmaxf(l0, l1);
        float e0 = __expf(l0 - mx);
        float e1 = __expf(l1 - mx);
        float inv = frcp(e0 + e1);
        float pr0 = e0 * inv, pr1 = e1 * inv;

        float per;
        if (pos) {
            float ce_pos = -(pr0 * LOG01 + pr1 * LOG09);
            float4 mb  = s_box[bidx];
            float2 mwh = s_wh[bidx];
            float invw = __fdividef(1.0f, rw);
            float invh = __fdividef(1.0f, rh);
            float tx = (mb.x - rx) * invw;
            float ty = (mb.y - ry) * invh;
            float tw = __logf(fmaxf(mwh.x * invw, 1e-8f));
            float th = __logf(fmaxf(mwh.y * invh, 1e-8f));
            float hx = huber1(tx - db[p]);
            float hy = huber1(ty - db[P_ + p]);
            float hw = huber1(tw - db[2 * P_ + p]);
            float hh = huber1(th - db[3 * P_ + p]);
            per = 2.0f * 0.25f * (hx + hy + hw + hh) + ce_pos;
        } else {
            float ce_neg = -(pr0 * LOG09 + pr1 * LOG01);
            per = (neg > 0) ? ce_neg : 0.0f;
        }
        per_sum += per;
    }

    // Deterministic block reduction
    s_red[tid] = per_sum;
    __syncthreads();
#pragma unroll
    for (int s = TPB / 2; s > 0; s >>= 1) {
        if (tid < s) s_red[tid] += s_red[tid + s];
        __syncthreads();
    }

    if (tid == 0) {
        g_partials[b * BLOCKS_PER_B + blockIdx.x] = s_red[0];
        __threadfence();
        unsigned t = atomicAdd(&g_count, 1u);
        s_last = (t == NB - 1);
    }
    __syncthreads();

    // Last block performs the fixed-order final reduction (deterministic:
    // identical summation order regardless of which block is last).
    if (s_last) {
        double acc = 0.0;
#pragma unroll
        for (int i = tid; i < NB; i += TPB)
            acc += (double)__ldcg(&g_partials[i]);
        s_d[tid] = acc;
        __syncthreads();
#pragma unroll
        for (int st = TPB / 2; st > 0; st >>= 1) {
            if (tid < st) s_d[tid] += s_d[tid + st];
            __syncthreads();
        }
        if (tid == 0) {
            out[0]  = (float)s_d[0];
            g_count = 0;   // reset for next graph replay
        }
    }
}

extern "C" void kernel_launch(void* const* d_in, const int* in_sizes, int n_in,
                              void* d_out, int out_size)
{
    const float* cls    = (const float*)d_in[0];  // [B, 2P]
    const float* deltas = (const float*)d_in[1];  // [B, 4P]
    const float* roi    = (const float*)d_in[2];  // [B, P, 4]
    const float* labels = (const float*)d_in[3];  // [B, L, 4]
    const int*   negf   = (const int*)  d_in[4];  // scalar

    dim3 grid(BLOCKS_PER_B, B_);
    classifier_loss_kernel<<<grid, TPB>>>(cls, deltas, roi, labels, negf,
                                          (float*)d_out);
    (void)in_sizes; (void)n_in; (void)out_size;
}

// round 7
// speedup vs baseline: 1.5114x; 1.1090x over previous
#include <cuda_runtime.h>
#include <cuda_bf16.h>

// Problem shapes (fixed by the dataset)
#define B_   128
#define P_   4096
#define L_   128
#define TPB  128
#define PPT  4                          // proposals per thread
#define BLOCKS_PER_B (P_ / (TPB * PPT)) // 8
#define NB   (B_ * BLOCKS_PER_B)        // 1024 partials

__device__ float        g_partials[NB];
__device__ unsigned int g_count = 0;

__device__ __forceinline__ float huber1(float e) {
    float a = fabsf(e);
    return (a <= 1.0f) ? 0.5f * e * e : a - 0.5f;
}

__device__ __forceinline__ float frcp(float x) {
    float r;
    asm("rcp.approx.f32 %0, %1;" : "=f"(r) : "f"(x));
    return r;
}

__global__ __launch_bounds__(TPB, 8)
void classifier_loss_kernel(const float* __restrict__ cls,
                            const float* __restrict__ deltas,
                            const float* __restrict__ roi,
                            const float* __restrict__ labels,
                            const int*   __restrict__ neg_flag,
                            float*       __restrict__ out)
{
    __shared__ float4 s_box[L_];   // lx, ly, lx+lw, ly+lh
    __shared__ float  s_la4[L_];   // 4*lw*lh
    __shared__ float2 s_wh[L_];    // lw, lh (exact, for targets)
    __shared__ float  s_red[TPB];
    __shared__ bool   s_last;
    __shared__ double s_d[TPB];

    const int tid = threadIdx.x;
    const int b   = blockIdx.y;
    const int pb  = blockIdx.x * (TPB * PPT) + tid;   // proposal base

    if (tid < L_) {
        float4 v = ((const float4*)(labels + (size_t)b * L_ * 4))[tid];
        s_box[tid] = make_float4(v.x, v.y, v.x + v.z, v.y + v.w);
        s_la4[tid] = 4.0f * v.z * v.w;
        s_wh[tid]  = make_float2(v.z, v.w);
    }
    __syncthreads();

    // Per-proposal state (SCALE=32 is an exact pow2 multiply)
    float rx[PPT], ry[PPT], rx2[PPT], ry2[PPT], rA4[PPT];
    unsigned best[PPT];
#pragma unroll
    for (int q = 0; q < PPT; ++q) {
        float4 r = ((const float4*)(roi + (size_t)b * P_ * 4))[pb + q * TPB];
        float x = r.x * 32.0f, y = r.y * 32.0f, w = r.z * 32.0f, h = r.w * 32.0f;
        rx[q] = x; ry[q] = y; rx2[q] = x + w; ry2[q] = y + h;
        rA4[q] = 4.0f * w * h;
        best[q] = 0u;
    }

    // argmax_l of iou == argmax_l of inter/(la + rA)  (monotone transform;
    // union = la + rA - inter, x -> x/(1+x) monotone).
    // Clamps done on the FMA pipe via d+|d| = 2*max(0,d); the factor 4 is
    // folded into the denominator (la4 + rA4). Packed-uint argmax: high 25
    // bits = score bits (score >= 0), low 7 bits = 127-l so the FIRST max
    // index wins ties (matches jnp.argmax).
#pragma unroll 4
    for (int l = 0; l < L_; ++l) {
        float4 lb  = s_box[l];
        float  la4 = s_la4[l];
        unsigned tag = (unsigned)(127 - l);
#pragma unroll
        for (int q = 0; q < PPT; ++q) {
            float dx = fminf(lb.z, rx2[q]) - fmaxf(lb.x, rx[q]);
            float dy = fminf(lb.w, ry2[q]) - fmaxf(lb.y, ry[q]);
            float sx = dx + fabsf(dx);          // 2*max(0,dx)  (FMA pipe)
            float sy = dy + fabsf(dy);          // 2*max(0,dy)
            float i4 = sx * sy;                 // 4*inter >= 0
            float sc = i4 * frcp(la4 + rA4[q]); // inter/(la+rA)
            unsigned pk = (__float_as_uint(sc) & 0xFFFFFF80u) | tag;
            best[q] = max(best[q], pk);
        }
    }

    const int neg = __ldg(neg_flag);
    const float LOG01 = -2.3025850929940457f;   // log(0.1)
    const float LOG09 = -0.10536051565782628f;  // log(0.9)
    const float* cb = cls    + (size_t)b * 2 * P_;
    const float* db = deltas + (size_t)b * 4 * P_;

    float per_sum = 0.0f;

#pragma unroll
    for (int q = 0; q < PPT; ++q) {
        const int p = pb + q * TPB;
        const unsigned be = best[q];

        int  bidx = 127 - (int)(be & 0x7Fu);
        bool pos  = ((be & 0xFFFFFF80u) != 0u) && (bidx > 0);

        float l0 = cb[p];
        float l1 = cb[P_ + p];
        float mx = fmaxf(l0, l1);
        float e0 = __expf(l0 - mx);
        float e1 = __expf(l1 - mx);
        float inv = frcp(e0 + e1);
        float pr0 = e0 * inv, pr1 = e1 * inv;

        float per;
        if (pos) {
            float ce_pos = -(pr0 * LOG01 + pr1 * LOG09);
            float4 mb  = s_box[bidx];
            float2 mwh = s_wh[bidx];
            float rw = rx2[q] - rx[q];          // ~1 ulp vs exact rw; fine
            float rh = ry2[q] - ry[q];
            float invw = __fdividef(1.0f, rw);
            float invh = __fdividef(1.0f, rh);
            float tx = (mb.x - rx[q]) * invw;
            float ty = (mb.y - ry[q]) * invh;
            float tw = __logf(fmaxf(mwh.x * invw, 1e-8f));
            float th = __logf(fmaxf(mwh.y * invh, 1e-8f));
            float hx = huber1(tx - db[p]);
            float hy = huber1(ty - db[P_ + p]);
            float hw = huber1(tw - db[2 * P_ + p]);
            float hh = huber1(th - db[3 * P_ + p]);
            per = 0.5f * (hx + hy + hw + hh) + ce_pos;   // 2 * mean(huber)
        } else {
            float ce_neg = -(pr0 * LOG09 + pr1 * LOG01);
            per = (neg > 0) ? ce_neg : 0.0f;
        }
        per_sum += per;
    }

    // Deterministic block reduction
    s_red[tid] = per_sum;
    __syncthreads();
#pragma unroll
    for (int s = TPB / 2; s > 0; s >>= 1) {
        if (tid < s) s_red[tid] += s_red[tid + s];
        __syncthreads();
    }

    if (tid == 0) {
        g_partials[b * BLOCKS_PER_B + blockIdx.x] = s_red[0];
        __threadfence();
        unsigned t = atomicAdd(&g_count, 1u);
        s_last = (t == NB - 1);
    }
    __syncthreads();

    // Last block does the fixed-order final reduction (deterministic:
    // identical summation order regardless of which block is last).
    if (s_last) {
        double acc = 0.0;
#pragma unroll
        for (int i = tid; i < NB; i += TPB)
            acc += (double)__ldcg(&g_partials[i]);
        s_d[tid] = acc;
        __syncthreads();
#pragma unroll
        for (int st = TPB / 2; st > 0; st >>= 1) {
            if (tid < st) s_d[tid] += s_d[tid + st];
            __syncthreads();
        }
        if (tid == 0) {
            out[0]  = (float)s_d[0];
            g_count = 0;   // reset for next graph replay
        }
    }
}

extern "C" void kernel_launch(void* const* d_in, const int* in_sizes, int n_in,
                              void* d_out, int out_size)
{
    const float* cls    = (const float*)d_in[0];  // [B, 2P]
    const float* deltas = (const float*)d_in[1];  // [B, 4P]
    const float* roi    = (const float*)d_in[2];  // [B, P, 4]
    const float* labels = (const float*)d_in[3];  // [B, L, 4]
    const int*   negf   = (const int*)  d_in[4];  // scalar

    dim3 grid(BLOCKS_PER_B, B_);
    classifier_loss_kernel<<<grid, TPB>>>(cls, deltas, roi, labels, negf,
                                          (float*)d_out);
    (void)in_sizes; (void)n_in; (void)out_size;
}

// round 8
// speedup vs baseline: 1.5315x; 1.0133x over previous
#include <cuda_runtime.h>
#include <cuda_bf16.h>

// Problem shapes (fixed by the dataset)
#define B_   128
#define P_   4096
#define L_   128
#define TPB  128
#define PPT  4                          // proposals per thread
#define BLOCKS_PER_B (P_ / (TPB * PPT)) // 8
#define NB   (B_ * BLOCKS_PER_B)        // 1024 partials

__device__ float        g_partials[NB];
__device__ unsigned int g_count = 0;

__device__ __forceinline__ float huber1(float e) {
    float a = fabsf(e);
    return (a <= 1.0f) ? 0.5f * e * e : a - 0.5f;
}

__device__ __forceinline__ float frcp(float x) {
    float r;
    asm("rcp.approx.f32 %0, %1;" : "=f"(r) : "f"(x));
    return r;
}

// a - b as FFMA(b, -1.0, a): bit-identical to FADD, but guaranteed on the
// FMA pipe and in the rt=1 immediate-multiplier form.
__device__ __forceinline__ float fsub_fma(float a, float b) {
    float d;
    asm("fma.rn.f32 %0, %1, 0fBF800000, %2;" : "=f"(d) : "f"(b), "f"(a));
    return d;
}
// x + y as FFMA(x, 1.0, y) — FMA pipe, imm form.
__device__ __forceinline__ float fadd_fma(float x, float y) {
    float d;
    asm("fma.rn.f32 %0, %1, 0f3F800000, %2;" : "=f"(d) : "f"(x), "f"(y));
    return d;
}

__global__ __launch_bounds__(TPB, 8)
void classifier_loss_kernel(const float* __restrict__ cls,
                            const float* __restrict__ deltas,
                            const float* __restrict__ roi,
                            const float* __restrict__ labels,
                            const int*   __restrict__ neg_flag,
                            float*       __restrict__ out)
{
    __shared__ float4 s_box[L_];   // lx, ly, lx+lw, ly+lh
    __shared__ float  s_la4[L_];   // 4*lw*lh
    __shared__ float2 s_wh[L_];    // lw, lh (exact, for targets)
    __shared__ float  s_red[TPB];
    __shared__ bool   s_last;
    __shared__ double s_d[TPB];

    const int tid = threadIdx.x;
    const int b   = blockIdx.y;
    const int pb  = blockIdx.x * (TPB * PPT) + tid;   // proposal base

    if (tid < L_) {
        float4 v = ((const float4*)(labels + (size_t)b * L_ * 4))[tid];
        s_box[tid] = make_float4(v.x, v.y, v.x + v.z, v.y + v.w);
        s_la4[tid] = 4.0f * v.z * v.w;
        s_wh[tid]  = make_float2(v.z, v.w);
    }
    __syncthreads();

    // Per-proposal state (SCALE=32 is an exact pow2 multiply)
    float rx[PPT], ry[PPT], rx2[PPT], ry2[PPT], rA4[PPT];
    unsigned best[PPT];
#pragma unroll
    for (int q = 0; q < PPT; ++q) {
        float4 r = ((const float4*)(roi + (size_t)b * P_ * 4))[pb + q * TPB];
        float x = r.x * 32.0f, y = r.y * 32.0f, w = r.z * 32.0f, h = r.w * 32.0f;
        rx[q] = x; ry[q] = y; rx2[q] = x + w; ry2[q] = y + h;
        rA4[q] = 4.0f * w * h;
        best[q] = 0u;
    }

    // argmax_l of iou == argmax_l of inter/(la + rA)  (monotone transform;
    // union = la + rA - inter, and x -> x/(1+x) is monotone).
    // All FP adds in the hot loop are FFMA-imm (fma pipe, rt=1); only the 4
    // FMNMX + LOP3 + IMNMX remain on the alu pipe.
    // Packed-uint argmax: high 25 bits = score bits (score >= 0), low 7 bits
    // = 127-l so the FIRST max index wins ties (matches jnp.argmax).
#pragma unroll 4
    for (int l = 0; l < L_; ++l) {
        float4 lb  = s_box[l];
        float  la4 = s_la4[l];
        unsigned tag = (unsigned)(127 - l);
#pragma unroll
        for (int q = 0; q < PPT; ++q) {
            float rc = frcp(fadd_fma(la4, rA4[q]));          // 1/(4(la+rA))
            float dx = fsub_fma(fminf(lb.z, rx2[q]), fmaxf(lb.x, rx[q]));
            float dy = fsub_fma(fminf(lb.w, ry2[q]), fmaxf(lb.y, ry[q]));
            float sx = fadd_fma(fabsf(dx), dx);              // 2*max(0,dx)
            float sy = fadd_fma(fabsf(dy), dy);              // 2*max(0,dy)
            float i4 = sx * sy;                              // 4*inter >= 0
            float sc = i4 * rc;                              // inter/(la+rA)
            unsigned pk = (__float_as_uint(sc) & 0xFFFFFF80u) | tag;
            best[q] = max(best[q], pk);
        }
    }

    const int neg = __ldg(neg_flag);
    const float LOG01 = -2.3025850929940457f;   // log(0.1)
    const float LOG09 = -0.10536051565782628f;  // log(0.9)
    const float* cb = cls    + (size_t)b * 2 * P_;
    const float* db = deltas + (size_t)b * 4 * P_;

    float per_sum = 0.0f;

#pragma unroll
    for (int q = 0; q < PPT; ++q) {
        const int p = pb + q * TPB;
        const unsigned be = best[q];

        int  bidx = 127 - (int)(be & 0x7Fu);
        bool pos  = ((be & 0xFFFFFF80u) != 0u) && (bidx > 0);

        float l0 = cb[p];
        float l1 = cb[P_ + p];
        float mx = fmaxf(l0, l1);
        float e0 = __expf(l0 - mx);
        float e1 = __expf(l1 - mx);
        float inv = frcp(e0 + e1);
        float pr0 = e0 * inv, pr1 = e1 * inv;

        float per;
        if (pos) {
            float ce_pos = -(pr0 * LOG01 + pr1 * LOG09);
            float4 mb  = s_box[bidx];
            float2 mwh = s_wh[bidx];
            float rw = rx2[q] - rx[q];          // ~1 ulp vs exact rw; fine
            float rh = ry2[q] - ry[q];
            float invw = __fdividef(1.0f, rw);
            float invh = __fdividef(1.0f, rh);
            float tx = (mb.x - rx[q]) * invw;
            float ty = (mb.y - ry[q]) * invh;
            float tw = __logf(fmaxf(mwh.x * invw, 1e-8f));
            float th = __logf(fmaxf(mwh.y * invh, 1e-8f));
            float hx = huber1(tx - db[p]);
            float hy = huber1(ty - db[P_ + p]);
            float hw = huber1(tw - db[2 * P_ + p]);
            float hh = huber1(th - db[3 * P_ + p]);
            per = 0.5f * (hx + hy + hw + hh) + ce_pos;   // 2 * mean(huber)
        } else {
            float ce_neg = -(pr0 * LOG09 + pr1 * LOG01);
            per = (neg > 0) ? ce_neg : 0.0f;
        }
        per_sum += per;
    }

    // Deterministic block reduction
    s_red[tid] = per_sum;
    __syncthreads();
#pragma unroll
    for (int s = TPB / 2; s > 0; s >>= 1) {
        if (tid < s) s_red[tid] += s_red[tid + s];
        __syncthreads();
    }

    if (tid == 0) {
        g_partials[b * BLOCKS_PER_B + blockIdx.x] = s_red[0];
        __threadfence();
        unsigned t = atomicAdd(&g_count, 1u);
        s_last = (t == NB - 1);
    }
    __syncthreads();

    // Last block does the fixed-order final reduction (deterministic:
    // identical summation order regardless of which block is last).
    if (s_last) {
        double acc = 0.0;
#pragma unroll
        for (int i = tid; i < NB; i += TPB)
            acc += (double)__ldcg(&g_partials[i]);
        s_d[tid] = acc;
        __syncthreads();
#pragma unroll
        for (int st = TPB / 2; st > 0; st >>= 1) {
            if (tid < st) s_d[tid] += s_d[tid + st];
            __syncthreads();
        }
        if (tid == 0) {
            out[0]  = (float)s_d[0];
            g_count = 0;   // reset for next graph replay
        }
    }
}

extern "C" void kernel_launch(void* const* d_in, const int* in_sizes, int n_in,
                              void* d_out, int out_size)
{
    const float* cls    = (const float*)d_in[0];  // [B, 2P]
    const float* deltas = (const float*)d_in[1];  // [B, 4P]
    const float* roi    = (const float*)d_in[2];  // [B, P, 4]
    const float* labels = (const float*)d_in[3];  // [B, L, 4]
    const int*   negf   = (const int*)  d_in[4];  // scalar

    dim3 grid(BLOCKS_PER_B, B_);
    classifier_loss_kernel<<<grid, TPB>>>(cls, deltas, roi, labels, negf,
                                          (float*)d_out);
    (void)in_sizes; (void)n_in; (void)out_size;
}